// round 2
// baseline (speedup 1.0000x reference)
#include <cuda_runtime.h>

#define B_    8
#define CI_   512
#define CO_   256
#define HW_   64
#define YP_   136      // padded y stride (y rows -1..130 live at 0..131; valid y r at r+1)
#define ZS_   128
#define COT   4        // output channels per block
#define CIT   4        // input channels per smem chunk
#define QT    13       // quad columns per block
#define NQ    5        // quads per thread (vertical strip): 13*5 = 65 rows exact
#define NTH   169

__device__ float g_km[CI_ * 9 * CO_];          // modulated, flipped: [ci][tap][co]
__device__ float g_y[B_ * CO_ * YP_ * YP_];    // padded intermediate (pad stays 0)

__device__ __forceinline__ void ffma2(unsigned long long& d, unsigned long long a, unsigned long long b) {
    asm("fma.rn.f32x2 %0, %1, %2, %0;" : "+l"(d) : "l"(a), "l"(b));
}
__device__ __forceinline__ float f2lo(unsigned long long v) { return __uint_as_float((unsigned)v); }
__device__ __forceinline__ float f2hi(unsigned long long v) { return __uint_as_float((unsigned)(v >> 32)); }

// ---------------- prep: demodulate + flip weights, layout [ci][tap][co] ----------------
__global__ void prep_kernel(const float* __restrict__ w) {
    __shared__ float red[256];
    const int o = blockIdx.x, tid = threadIdx.x;
    const float wsc = 1.0f / sqrtf((float)(CI_ * 9));
    const float* wo = w + o * (CI_ * 9);
    float s = 0.f;
    for (int idx = tid; idx < CI_ * 9; idx += 256) {
        float v = wo[idx] * wsc;
        s += v * v;
    }
    red[tid] = s;
    __syncthreads();
    for (int st = 128; st > 0; st >>= 1) {
        if (tid < st) red[tid] += red[tid + st];
        __syncthreads();
    }
    const float scale = wsc * rsqrtf(red[0] + 1e-6f);
    for (int idx = tid; idx < CI_ * 9; idx += 256) {
        int i = idx / 9, t = idx % 9, kh = t / 3, kw = t % 3;
        float v = wo[i * 9 + (2 - kh) * 3 + (2 - kw)] * scale;   // spatial flip
        g_km[idx * CO_ + o] = v;                                 // idx == i*9+t
    }
}

// ---------------- transposed conv, quad-decomposed, 5-quad vertical register blocking ----------------
// tap -> (x row sel, x col sel, pixel):
//   t0:(0,0)p0  t1:(0,1)p1  t2:(0,1)p0  t3:(1,0)p2  t4:(1,1)p3
//   t5:(1,1)p2  t6:(1,0)p0  t7:(1,1)p1  t8:(1,1)p0
__global__ void __launch_bounds__(NTH, 2) conv_kernel(const float* __restrict__ x, int co_base) {
    __shared__ float2 xs[CIT][67][14];          // x tile, duplicated (v,v) for f32x2
    __shared__ ulonglong2 wsm[CIT][9];          // 4 co per (ci,tap): pairs (c0,c1),(c2,c3)

    const int tid = threadIdx.x;
    const int bb   = blockIdx.z >> 5;           // batch
    const int tile = blockIdx.z & 31;
    const int co0  = co_base + tile * COT;
    const int B0   = blockIdx.x * QT;
    const int qy   = tid / QT;                  // 0..12 -> quad rows 5qy..5qy+4
    const int qx   = tid % QT;

    unsigned long long acc[NQ][4][2];           // [quad][pixel][co-pair]
#pragma unroll
    for (int q = 0; q < NQ; q++)
#pragma unroll
        for (int p = 0; p < 4; p++) { acc[q][p][0] = 0ull; acc[q][p][1] = 0ull; }

    const float* xb = x + (size_t)bb * CI_ * HW_ * HW_;
    float* wsf = (float*)wsm;

    constexpr int RI[9] = {0,0,0,1,1,1,1,1,1};
    constexpr int CJ[9] = {0,1,1,0,1,1,0,1,1};
    constexpr int PP[9] = {0,1,0,2,3,2,0,1,0};

    for (int cc = 0; cc < CI_; cc += CIT) {
        __syncthreads();
        // stage x tile: rows -1..65 (67), cols B0-1..B0+12 (14)
        for (int idx = tid; idx < CIT * 67 * 14; idx += NTH) {
            int ci = idx / (67 * 14), rem = idx % (67 * 14), r = rem / 14, c = rem % 14;
            int iy = r - 1, ix = B0 - 1 + c;
            float v = 0.f;
            if ((unsigned)iy < HW_ && (unsigned)ix < HW_)
                v = xb[((cc + ci) * HW_ + iy) * HW_ + ix];
            xs[ci][r][c] = make_float2(v, v);
        }
        // stage weights
        for (int idx = tid; idx < CIT * 9 * COT; idx += NTH) {
            int ci = idx / (9 * COT), rem = idx % (9 * COT), t = rem / COT, c = rem % COT;
            wsf[idx] = g_km[((cc + ci) * 9 + t) * CO_ + co0 + c];
        }
        __syncthreads();
#pragma unroll
        for (int ci = 0; ci < CIT; ci++) {
            unsigned long long xr[NQ + 1][2];
#pragma unroll
            for (int i = 0; i <= NQ; i++) {
                xr[i][0] = *(const unsigned long long*)&xs[ci][NQ * qy + i][qx];
                xr[i][1] = *(const unsigned long long*)&xs[ci][NQ * qy + i][qx + 1];
            }
#pragma unroll
            for (int t = 0; t < 9; t++) {
                ulonglong2 kk = wsm[ci][t];
#pragma unroll
                for (int q = 0; q < NQ; q++) {
                    unsigned long long xv = xr[q + RI[t]][CJ[t]];
                    ffma2(acc[q][PP[t]][0], xv, kk.x);
                    ffma2(acc[q][PP[t]][1], xv, kk.y);
                }
            }
        }
    }

    // epilogue: write padded y
    const int a0 = NQ * qy;
    const int ox = 2 * (B0 + qx);
    const bool c1 = ox < 128;
    float* ybase = g_y + (size_t)(bb * CO_ + co0) * (YP_ * YP_);
#pragma unroll
    for (int q = 0; q < NQ; q++) {
        const int oy = 2 * (a0 + q);
        const bool r1 = oy < 128;
        const size_t base = (size_t)(oy + 1) * YP_ + (ox + 1);
#pragma unroll
        for (int j = 0; j < 2; j++)
#pragma unroll
            for (int h = 0; h < 2; h++) {
                float* yco = ybase + (size_t)(2 * j + h) * (YP_ * YP_);
                float v0 = h ? f2hi(acc[q][0][j]) : f2lo(acc[q][0][j]);
                float v1 = h ? f2hi(acc[q][1][j]) : f2lo(acc[q][1][j]);
                float v2 = h ? f2hi(acc[q][2][j]) : f2lo(acc[q][2][j]);
                float v3 = h ? f2hi(acc[q][3][j]) : f2lo(acc[q][3][j]);
                yco[base] = v0;
                if (c1) yco[base + 1] = v1;
                if (r1) yco[base + YP_] = v2;
                if (r1 && c1) yco[base + YP_ + 1] = v3;
            }
    }
}

// ---------------- depthwise 4x4 FIR blur, separable row-streaming ----------------
__global__ void blur_kernel(float* __restrict__ z, int co_base) {
    const int cx = threadIdx.x;                  // 0..31 -> out cols 4cx..4cx+3
    const int ry = threadIdx.y;                  // 0..7  -> out rows 16ry..16ry+15
    const int bc = blockIdx.z;
    const int b = bc >> 7;
    const int col = co_base + (bc & 127);
    const float* yb = g_y + (size_t)(b * CO_ + col) * (YP_ * YP_);
    float* zb = z + (size_t)(b * CO_ + col) * (ZS_ * ZS_);
    const int c0 = cx * 4;
    const int zy0 = ry * 16;

    float4 h0 = {}, h1 = {}, h2 = {};
#pragma unroll
    for (int k = 0; k < 19; k++) {
        const float* row = yb + (size_t)(zy0 + k) * YP_ + c0;
        float4 a = *(const float4*)row;
        float4 e = *(const float4*)(row + 4);
        float4 h;
        h.x = a.x + 3.f * a.y + 3.f * a.z + a.w;
        h.y = a.y + 3.f * a.z + 3.f * a.w + e.x;
        h.z = a.z + 3.f * a.w + 3.f * e.x + e.y;
        h.w = a.w + 3.f * e.x + 3.f * e.y + e.z;
        if (k >= 3) {
            float4 o;
            o.x = (h0.x + 3.f * h1.x + 3.f * h2.x + h.x) * 0.0625f;
            o.y = (h0.y + 3.f * h1.y + 3.f * h2.y + h.y) * 0.0625f;
            o.z = (h0.z + 3.f * h1.z + 3.f * h2.z + h.z) * 0.0625f;
            o.w = (h0.w + 3.f * h1.w + 3.f * h2.w + h.w) * 0.0625f;
            *(float4*)&zb[(size_t)(zy0 + k - 3) * ZS_ + c0] = o;
        }
        h0 = h1; h1 = h2; h2 = h;
    }
}

extern "C" void kernel_launch(void* const* d_in, const int* in_sizes, int n_in,
                              void* d_out, int out_size) {
    const float* x = (const float*)d_in[0];
    const float* w = (const float*)d_in[1];
    float* z = (float*)d_out;
    prep_kernel<<<CO_, 256>>>(w);
    conv_kernel<<<dim3(5, 1, B_ * 32), NTH>>>(x, 0);      // co 0..127
    blur_kernel<<<dim3(1, 1, B_ * 128), dim3(32, 8)>>>(z, 0);
    conv_kernel<<<dim3(5, 1, B_ * 32), NTH>>>(x, 128);    // co 128..255 (ncu position 3)
    blur_kernel<<<dim3(1, 1, B_ * 128), dim3(32, 8)>>>(z, 128);
}